// round 14
// baseline (speedup 1.0000x reference)
#include <cuda_runtime.h>
#include <cstdint>

// LocalLayer: y[8192,4096] = x @ W.T + b, W banded. For window group g
// (outs 64g..64g+63) all nonzero W cols lie in [clamp(64g-32,0,3968), +128).
// CTA: fixed g, M128xN64xK128 tiles (2 chained); warp tile M32xN32;
// tf32 mma.sync; cp.async 4-deep ring-buffered A staging at K=16 granularity.

#define IN_F   4096
#define OUT_F  4096
#define NBATCH 8192
#define KTILE  128
#define KH     16          // K slice per pipeline stage
#define MTILE  128
#define CHUNK  2           // tiles per CTA
#define NSTAGE (CHUNK * (KTILE / KH))   // 16 stages
#define NBUF   4
#define NTHR   256

#define PB     132         // B smem pitch (floats); 528B stride conflict-free
#define PA     20          // A buf pitch (floats); 80B stride, ldmatrix conflict-free
#define B_FLOATS    (64 * PB)            // 8448
#define ABUF_FLOATS (MTILE * PA)         // 2560
#define SMEM_FLOATS (B_FLOATS + NBUF * ABUF_FLOATS)  // 18688
#define SMEM_TOTAL  (SMEM_FLOATS * 4)                // 74752 B -> 3 CTAs/SM

__device__ __forceinline__ uint32_t smem_u32(const void* p) {
    uint32_t a;
    asm("{ .reg .u64 t; cvta.to.shared.u64 t, %1; cvt.u32.u64 %0, t; }" : "=r"(a) : "l"(p));
    return a;
}
__device__ __forceinline__ uint32_t to_tf32(float f) {
    uint32_t r;
    asm("cvt.rna.tf32.f32 %0, %1;" : "=r"(r) : "f"(f));
    return r;
}
__device__ __forceinline__ void ldsm_x4(uint32_t* r, uint32_t addr) {
    asm volatile("ldmatrix.sync.aligned.m8n8.x4.shared.b16 {%0,%1,%2,%3}, [%4];"
                 : "=r"(r[0]), "=r"(r[1]), "=r"(r[2]), "=r"(r[3]) : "r"(addr));
}
__device__ __forceinline__ void mma_tf32(float* c, const uint32_t* a,
                                         uint32_t b0, uint32_t b1) {
    asm volatile(
        "mma.sync.aligned.m16n8k8.row.col.f32.tf32.tf32.f32 "
        "{%0,%1,%2,%3}, {%4,%5,%6,%7}, {%8,%9}, {%0,%1,%2,%3};"
        : "+f"(c[0]), "+f"(c[1]), "+f"(c[2]), "+f"(c[3])
        : "r"(a[0]), "r"(a[1]), "r"(a[2]), "r"(a[3]), "r"(b0), "r"(b1));
}
__device__ __forceinline__ void cp_async16(uint32_t dst, const void* src) {
    asm volatile("cp.async.cg.shared.global [%0], [%1], 16;" :: "r"(dst), "l"(src));
}
__device__ __forceinline__ int clampi(int v, int lo, int hi) {
    return v < lo ? lo : (v > hi ? hi : v);
}

extern "C" __global__ void __launch_bounds__(NTHR, 3)
local_layer_mma_ring(const float* __restrict__ x,
                     const float* __restrict__ W,
                     const float* __restrict__ b,
                     float* __restrict__ y)
{
    extern __shared__ float smem[];
    float* Bs = smem;                          // [64][PB] tf32 bits
    float* Ab[NBUF];
    #pragma unroll
    for (int i = 0; i < NBUF; i++) Ab[i] = smem + B_FLOATS + i * ABUF_FLOATS;

    const int g  = blockIdx.y;                 // 64 groups
    const int cm = blockIdx.x;                 // 32 row chunks (256 rows each)
    const int rbase0 = cm * (MTILE * CHUNK);
    const int jbp = clampi(64 * g - 32, 0, IN_F - KTILE);

    const int tid  = threadIdx.x;
    const int w    = tid >> 5;
    const int lane = tid & 31;

    // ---- stage B = W[64g..+64][jbp..+128) as tf32 (once per CTA) ----
    #pragma unroll
    for (int i = 0; i < 8; i++) {
        int idx = tid + NTHR * i;              // 0..2047
        int row = idx >> 5;
        int c4  = idx & 31;
        const float4 v = *(const float4*)(W + (size_t)(64 * g + row) * IN_F + jbp + 4 * c4);
        uint4 t;
        t.x = to_tf32(v.x); t.y = to_tf32(v.y); t.z = to_tf32(v.z); t.w = to_tf32(v.w);
        *(uint4*)(Bs + row * PB + 4 * c4) = t;
    }

    // A stage issue: stage q -> tile q>>3, kslice q&7, buffer q&3
    auto issue_stage = [&](int q) {
        const int tile = q >> 3, kq = q & 7;
        const float* src_base = x + (size_t)(rbase0 + tile * MTILE) * IN_F + jbp + kq * KH;
        float* dstb = Ab[q & (NBUF - 1)];
        #pragma unroll
        for (int i = 0; i < 2; i++) {
            int idx = tid + NTHR * i;          // 0..511
            int row = idx >> 2;                // 0..127
            int c4  = idx & 3;                 // 0..3 (16 floats per row)
            cp_async16(smem_u32(dstb + row * PA + 4 * c4),
                       src_base + (size_t)row * IN_F + 4 * c4);
        }
    };

    issue_stage(0);
    asm volatile("cp.async.commit_group;" ::: "memory");
    issue_stage(1);
    asm volatile("cp.async.commit_group;" ::: "memory");
    issue_stage(2);
    asm volatile("cp.async.commit_group;" ::: "memory");

    // ---- warp mapping: 4x2 grid of M32 x N32 warp tiles ----
    const int mrow  = (w & 3) * 32;
    const int nbase = (w >> 2) * 32;
    const int q_  = lane >> 3;
    const int lr  = lane & 7;
    const int gg  = lane >> 2;
    const int tt  = lane & 3;

    uint32_t a_base[NBUF][2];                  // [buf][mt]
    #pragma unroll
    for (int bufi = 0; bufi < NBUF; bufi++)
        #pragma unroll
        for (int mt = 0; mt < 2; mt++)
            a_base[bufi][mt] = smem_u32(Ab[bufi]
                + (mrow + mt * 16 + (q_ & 1) * 8 + lr) * PA + (q_ >> 1) * 4);
    uint32_t b_addr[2];
    #pragma unroll
    for (int nb = 0; nb < 2; nb++)
        b_addr[nb] = smem_u32(Bs + (nbase + nb * 16 + (q_ >> 1) * 8 + lr) * PB + (q_ & 1) * 4);

    float acc[2][4][4];
    #pragma unroll
    for (int mt = 0; mt < 2; mt++)
        #pragma unroll
        for (int nt = 0; nt < 4; nt++)
            #pragma unroll
            for (int c = 0; c < 4; c++) acc[mt][nt][c] = 0.0f;

    #pragma unroll
    for (int s = 0; s < NSTAGE; s++) {
        asm volatile("cp.async.wait_group 2;" ::: "memory");
        __syncthreads();

        const int kq  = s & 7;
        const int buf = s & (NBUF - 1);

        #pragma unroll
        for (int ks = 0; ks < 2; ks++) {       // K8 steps within KH=16
            uint32_t ar0[4], ar1[4], bf0[4], bf1[4];
            ldsm_x4(ar0, a_base[buf][0] + ks * 32);
            ldsm_x4(ar1, a_base[buf][1] + ks * 32);
            ldsm_x4(bf0, b_addr[0] + kq * 64 + ks * 32);
            ldsm_x4(bf1, b_addr[1] + kq * 64 + ks * 32);
            #pragma unroll
            for (int i = 0; i < 4; i++) {
                ar0[i] = to_tf32(__uint_as_float(ar0[i]));
                ar1[i] = to_tf32(__uint_as_float(ar1[i]));
            }
            mma_tf32(acc[0][0], ar0, bf0[0], bf0[1]);
            mma_tf32(acc[0][1], ar0, bf0[2], bf0[3]);
            mma_tf32(acc[0][2], ar0, bf1[0], bf1[1]);
            mma_tf32(acc[0][3], ar0, bf1[2], bf1[3]);
            mma_tf32(acc[1][0], ar1, bf0[0], bf0[1]);
            mma_tf32(acc[1][1], ar1, bf0[2], bf0[3]);
            mma_tf32(acc[1][2], ar1, bf1[0], bf1[1]);
            mma_tf32(acc[1][3], ar1, bf1[2], bf1[3]);
        }

        if (kq == 7) {
            // epilogue for tile s>>3: direct STG.64 with bias (L1-hot)
            const int tile = s >> 3;
            #pragma unroll
            for (int mt = 0; mt < 2; mt++) {
                const int r0 = rbase0 + tile * MTILE + mrow + mt * 16 + gg;
                #pragma unroll
                for (int nt = 0; nt < 4; nt++) {
                    const int gcol = 64 * g + nbase + nt * 8 + 2 * tt;
                    const float2 bv = *(const float2*)(b + gcol);
                    float* c = acc[mt][nt];
                    *(float2*)(y + (size_t)r0 * OUT_F + gcol) =
                        make_float2(c[0] + bv.x, c[1] + bv.y);
                    *(float2*)(y + (size_t)(r0 + 8) * OUT_F + gcol) =
                        make_float2(c[2] + bv.x, c[3] + bv.y);
                    #pragma unroll
                    for (int cc = 0; cc < 4; cc++) c[cc] = 0.0f;
                }
            }
        }
        __syncthreads();

        if (s + 3 < NSTAGE) issue_stage(s + 3);
        asm volatile("cp.async.commit_group;" ::: "memory");
    }
}

extern "C" void kernel_launch(void* const* d_in, const int* in_sizes, int n_in,
                              void* d_out, int out_size) {
    const float* x = (const float*)d_in[0];
    const float* W = (const float*)d_in[1];
    const float* b = (const float*)d_in[2];
    // d_in[3] = mask, unused (already baked into W at init)
    float* y = (float*)d_out;

    cudaFuncSetAttribute(local_layer_mma_ring,
                         cudaFuncAttributeMaxDynamicSharedMemorySize, SMEM_TOTAL);

    dim3 grid(NBATCH / (MTILE * CHUNK), OUT_F / 64);   // 32 x 64
    local_layer_mma_ring<<<grid, NTHR, SMEM_TOTAL>>>(x, W, b, y);
}

// round 15
// speedup vs baseline: 1.6104x; 1.6104x over previous
#include <cuda_runtime.h>
#include <cstdint>

// LocalLayer: y[8192,4096] = x @ W.T + b, W banded. For window group g
// (outs 64g..64g+63) all nonzero W cols lie in [clamp(64g-32,0,3968), +128).
// CTA: fixed g, M128xN64xK128 tiles (2 chained); warp tile M32xN32;
// tf32 mma.sync; cp.async 3-deep ring A staging (KH=32), 1 sync/stage.

#define IN_F   4096
#define OUT_F  4096
#define NBATCH 8192
#define KTILE  128
#define KH     32          // K quarter per pipeline stage
#define MTILE  128
#define CHUNK  2           // tiles per CTA
#define NSTAGE (CHUNK * (KTILE / KH))   // 8 stages
#define NBUF   3
#define NTHR   256

#define PB     132         // B smem pitch (floats); 528B stride conflict-free
#define PA     36          // A buf pitch (floats); 144B stride conflict-free
#define B_FLOATS    (64 * PB)            // 8448
#define ABUF_FLOATS (MTILE * PA)         // 4608
#define SMEM_FLOATS (B_FLOATS + NBUF * ABUF_FLOATS)  // 22272
#define SMEM_TOTAL  (SMEM_FLOATS * 4)                // 89088 B -> 2 CTAs/SM

__device__ __forceinline__ uint32_t smem_u32(const void* p) {
    uint32_t a;
    asm("{ .reg .u64 t; cvta.to.shared.u64 t, %1; cvt.u32.u64 %0, t; }" : "=r"(a) : "l"(p));
    return a;
}
__device__ __forceinline__ uint32_t to_tf32(float f) {
    uint32_t r;
    asm("cvt.rna.tf32.f32 %0, %1;" : "=r"(r) : "f"(f));
    return r;
}
__device__ __forceinline__ void ldsm_x4(uint32_t* r, uint32_t addr) {
    asm volatile("ldmatrix.sync.aligned.m8n8.x4.shared.b16 {%0,%1,%2,%3}, [%4];"
                 : "=r"(r[0]), "=r"(r[1]), "=r"(r[2]), "=r"(r[3]) : "r"(addr));
}
__device__ __forceinline__ void mma_tf32(float* c, const uint32_t* a,
                                         uint32_t b0, uint32_t b1) {
    asm volatile(
        "mma.sync.aligned.m16n8k8.row.col.f32.tf32.tf32.f32 "
        "{%0,%1,%2,%3}, {%4,%5,%6,%7}, {%8,%9}, {%0,%1,%2,%3};"
        : "+f"(c[0]), "+f"(c[1]), "+f"(c[2]), "+f"(c[3])
        : "r"(a[0]), "r"(a[1]), "r"(a[2]), "r"(a[3]), "r"(b0), "r"(b1));
}
__device__ __forceinline__ void cp_async16(uint32_t dst, const void* src) {
    asm volatile("cp.async.cg.shared.global [%0], [%1], 16;" :: "r"(dst), "l"(src));
}
__device__ __forceinline__ int clampi(int v, int lo, int hi) {
    return v < lo ? lo : (v > hi ? hi : v);
}

extern "C" __global__ void __launch_bounds__(NTHR, 2)
local_layer_mma_ring3(const float* __restrict__ x,
                      const float* __restrict__ W,
                      const float* __restrict__ b,
                      float* __restrict__ y)
{
    extern __shared__ float smem[];
    float* Bs = smem;                          // [64][PB] tf32 bits
    float* Ab[NBUF];
    #pragma unroll
    for (int i = 0; i < NBUF; i++) Ab[i] = smem + B_FLOATS + i * ABUF_FLOATS;

    const int g  = blockIdx.y;                 // 64 groups
    const int cm = blockIdx.x;                 // 32 row chunks (256 rows each)
    const int rbase0 = cm * (MTILE * CHUNK);
    const int jbp = clampi(64 * g - 32, 0, IN_F - KTILE);

    const int tid  = threadIdx.x;
    const int w    = tid >> 5;
    const int lane = tid & 31;

    // ---- stage B = W[64g..+64][jbp..+128) as tf32 (once per CTA) ----
    #pragma unroll
    for (int i = 0; i < 8; i++) {
        int idx = tid + NTHR * i;              // 0..2047
        int row = idx >> 5;
        int c4  = idx & 31;
        const float4 v = *(const float4*)(W + (size_t)(64 * g + row) * IN_F + jbp + 4 * c4);
        uint4 t;
        t.x = to_tf32(v.x); t.y = to_tf32(v.y); t.z = to_tf32(v.z); t.w = to_tf32(v.w);
        *(uint4*)(Bs + row * PB + 4 * c4) = t;
    }

    // A stage issue: stage q -> tile q>>2, kquarter q&3, buffer q%3
    auto issue_stage = [&](int q) {
        const int tile = q >> 2, kq = q & 3;
        const float* src_base = x + (size_t)(rbase0 + tile * MTILE) * IN_F + jbp + kq * KH;
        float* dstb = Ab[q % NBUF];
        #pragma unroll
        for (int i = 0; i < 4; i++) {
            int idx = tid + NTHR * i;          // 0..1023
            int row = idx >> 3;                // 0..127
            int c4  = idx & 7;                 // 0..7 (32 floats per row)
            cp_async16(smem_u32(dstb + row * PA + 4 * c4),
                       src_base + (size_t)row * IN_F + 4 * c4);
        }
    };

    issue_stage(0);
    asm volatile("cp.async.commit_group;" ::: "memory");
    issue_stage(1);
    asm volatile("cp.async.commit_group;" ::: "memory");

    // ---- warp mapping: 4x2 grid of M32 x N32 warp tiles ----
    const int mrow  = (w & 3) * 32;
    const int nbase = (w >> 2) * 32;
    const int q_  = lane >> 3;
    const int lr  = lane & 7;
    const int gg  = lane >> 2;
    const int tt  = lane & 3;

    uint32_t a_base[NBUF][2];                  // [buf][mt]
    #pragma unroll
    for (int bufi = 0; bufi < NBUF; bufi++)
        #pragma unroll
        for (int mt = 0; mt < 2; mt++)
            a_base[bufi][mt] = smem_u32(Ab[bufi]
                + (mrow + mt * 16 + (q_ & 1) * 8 + lr) * PA + (q_ >> 1) * 4);
    uint32_t b_addr[2];
    #pragma unroll
    for (int nb = 0; nb < 2; nb++)
        b_addr[nb] = smem_u32(Bs + (nbase + nb * 16 + (q_ >> 1) * 8 + lr) * PB + (q_ & 1) * 4);

    float acc[2][4][4];
    #pragma unroll
    for (int mt = 0; mt < 2; mt++)
        #pragma unroll
        for (int nt = 0; nt < 4; nt++)
            #pragma unroll
            for (int c = 0; c < 4; c++) acc[mt][nt][c] = 0.0f;

    #pragma unroll
    for (int s = 0; s < NSTAGE; s++) {
        // stage s arrived (<=1 group pending: stage s+1)
        asm volatile("cp.async.wait_group 1;" ::: "memory");
        __syncthreads();   // also fences stage s-1 reads of buf[(s+2)%3]

        // issue stage s+2 into buf[(s+2)%3] (consumed last at stage s-1)
        if (s + 2 < NSTAGE) issue_stage(s + 2);
        asm volatile("cp.async.commit_group;" ::: "memory");

        const int kq  = s & 3;
        const int buf = s % NBUF;

        #pragma unroll
        for (int ks = 0; ks < 4; ks++) {       // K8 steps within KH=32
            uint32_t ar0[4], ar1[4], bf0[4], bf1[4];
            ldsm_x4(ar0, a_base[buf][0] + ks * 32);
            ldsm_x4(ar1, a_base[buf][1] + ks * 32);
            ldsm_x4(bf0, b_addr[0] + kq * 128 + ks * 32);
            ldsm_x4(bf1, b_addr[1] + kq * 128 + ks * 32);
            #pragma unroll
            for (int i = 0; i < 4; i++) {
                ar0[i] = to_tf32(__uint_as_float(ar0[i]));
                ar1[i] = to_tf32(__uint_as_float(ar1[i]));
            }
            mma_tf32(acc[0][0], ar0, bf0[0], bf0[1]);
            mma_tf32(acc[0][1], ar0, bf0[2], bf0[3]);
            mma_tf32(acc[0][2], ar0, bf1[0], bf1[1]);
            mma_tf32(acc[0][3], ar0, bf1[2], bf1[3]);
            mma_tf32(acc[1][0], ar1, bf0[0], bf0[1]);
            mma_tf32(acc[1][1], ar1, bf0[2], bf0[3]);
            mma_tf32(acc[1][2], ar1, bf1[0], bf1[1]);
            mma_tf32(acc[1][3], ar1, bf1[2], bf1[3]);
        }

        if (kq == 3) {
            // epilogue for tile s>>2: direct STG.64 with bias (L1-hot)
            const int tile = s >> 2;
            #pragma unroll
            for (int mt = 0; mt < 2; mt++) {
                const int r0 = rbase0 + tile * MTILE + mrow + mt * 16 + gg;
                #pragma unroll
                for (int nt = 0; nt < 4; nt++) {
                    const int gcol = 64 * g + nbase + nt * 8 + 2 * tt;
                    const float2 bv = *(const float2*)(b + gcol);
                    float* c = acc[mt][nt];
                    *(float2*)(y + (size_t)r0 * OUT_F + gcol) =
                        make_float2(c[0] + bv.x, c[1] + bv.y);
                    *(float2*)(y + (size_t)(r0 + 8) * OUT_F + gcol) =
                        make_float2(c[2] + bv.x, c[3] + bv.y);
                    #pragma unroll
                    for (int cc = 0; cc < 4; cc++) c[cc] = 0.0f;
                }
            }
        }
    }
}

extern "C" void kernel_launch(void* const* d_in, const int* in_sizes, int n_in,
                              void* d_out, int out_size) {
    const float* x = (const float*)d_in[0];
    const float* W = (const float*)d_in[1];
    const float* b = (const float*)d_in[2];
    // d_in[3] = mask, unused (already baked into W at init)
    float* y = (float*)d_out;

    cudaFuncSetAttribute(local_layer_mma_ring3,
                         cudaFuncAttributeMaxDynamicSharedMemorySize, SMEM_TOTAL);

    dim3 grid(NBATCH / (MTILE * CHUNK), OUT_F / 64);   // 32 x 64
    local_layer_mma_ring3<<<grid, NTHR, SMEM_TOTAL>>>(x, W, b, y);
}